// round 2
// baseline (speedup 1.0000x reference)
#include <cuda_runtime.h>

// Problem constants
#define S_LEN   512
#define HDIM    1024
#define BATCH   64
#define IDIM    1024
#define M_TOT   (BATCH * S_LEN)          // 32768
#define OUT_TAIL (BATCH * S_LEN * HDIM)  // offset of h_last region in d_out

// ====================================================================
// Kernel 1: input projection GEMM
//   C[m, n] = sum_i A[m,i] * Wih[n,i] + (bih[n] + bhh[n])
//   A = inputs viewed as [32768, 1024] (m = b*512 + s), C written into
//   d_out's outputs region (same [m, n] layout as [B,S,H]).
// 128x128 tile, BK=16, 256 threads, 8x8 per-thread micro-tile.
// ====================================================================
__global__ void __launch_bounds__(256) xproj_kernel(
    const float* __restrict__ A,
    const float* __restrict__ W,
    const float* __restrict__ bih,
    const float* __restrict__ bhh,
    float* __restrict__ C)
{
    __shared__ float As[16][132];   // [k][m], padded (132 keeps 16B align + 2-way max conflicts)
    __shared__ float Bs[16][132];   // [k][n]

    const int tid = threadIdx.x;
    const int tx  = tid & 15;       // 0..15 -> n
    const int ty  = tid >> 4;       // 0..15 -> m
    const int m0  = blockIdx.y * 128;
    const int n0  = blockIdx.x * 128;

    float acc[8][8];
#pragma unroll
    for (int i = 0; i < 8; i++)
#pragma unroll
        for (int j = 0; j < 8; j++) acc[i][j] = 0.0f;

    const float4* A4 = (const float4*)A;
    const float4* W4 = (const float4*)W;

    for (int k0 = 0; k0 < IDIM; k0 += 16) {
        const int kq = k0 >> 2;
        // load 128x16 tiles of A and W (512 float4 each; 2 per thread)
#pragma unroll
        for (int q = 0; q < 2; q++) {
            int f  = q * 256 + tid;   // 0..511
            int r  = f >> 2;          // row within tile (0..127)
            int c4 = f & 3;           // k-quad (0..3)
            float4 av = A4[(size_t)(m0 + r) * 256 + kq + c4];
            As[c4 * 4 + 0][r] = av.x;
            As[c4 * 4 + 1][r] = av.y;
            As[c4 * 4 + 2][r] = av.z;
            As[c4 * 4 + 3][r] = av.w;
            float4 bv = W4[(size_t)(n0 + r) * 256 + kq + c4];
            Bs[c4 * 4 + 0][r] = bv.x;
            Bs[c4 * 4 + 1][r] = bv.y;
            Bs[c4 * 4 + 2][r] = bv.z;
            Bs[c4 * 4 + 3][r] = bv.w;
        }
        __syncthreads();

#pragma unroll
        for (int kk = 0; kk < 16; kk++) {
            float ra[8], rb[8];
            *(float4*)&ra[0] = *(const float4*)&As[kk][ty * 4];
            *(float4*)&ra[4] = *(const float4*)&As[kk][64 + ty * 4];
            *(float4*)&rb[0] = *(const float4*)&Bs[kk][tx * 4];
            *(float4*)&rb[4] = *(const float4*)&Bs[kk][64 + tx * 4];
#pragma unroll
            for (int i = 0; i < 8; i++)
#pragma unroll
                for (int j = 0; j < 8; j++)
                    acc[i][j] = fmaf(ra[i], rb[j], acc[i][j]);
        }
        __syncthreads();
    }

    // epilogue: bias add + store
    float bsum[8];
#pragma unroll
    for (int j = 0; j < 8; j++) {
        int n = n0 + ((j < 4) ? (tx * 4 + j) : (64 + tx * 4 + (j - 4)));
        bsum[j] = bih[n] + bhh[n];
    }
#pragma unroll
    for (int i = 0; i < 8; i++) {
        int m = m0 + ((i < 4) ? (ty * 4 + i) : (64 + ty * 4 + (i - 4)));
        float4 v0, v1;
        v0.x = acc[i][0] + bsum[0]; v0.y = acc[i][1] + bsum[1];
        v0.z = acc[i][2] + bsum[2]; v0.w = acc[i][3] + bsum[3];
        v1.x = acc[i][4] + bsum[4]; v1.y = acc[i][5] + bsum[5];
        v1.z = acc[i][6] + bsum[6]; v1.w = acc[i][7] + bsum[7];
        *(float4*)&C[(size_t)m * HDIM + n0 + tx * 4]      = v0;
        *(float4*)&C[(size_t)m * HDIM + n0 + 64 + tx * 4] = v1;
    }
}

// ====================================================================
// Kernel 2: persistent recurrence.
//   Grid = 128 CTAs = 4 batch-groups (16 batch each) x 32 CTAs (32 output
//   neurons each). W_hh slice lives in SMEM for the whole kernel.
//   Per step: load group h into SMEM, compute relu(xp + h @ Whh^T) for
//   the (16 x 32) tile, write to d_out + h ping-pong buffer, group barrier.
// ====================================================================
#define WSTR 1028                       // padded row stride (floats): conflict-free LDS.128
#define REC_SMEM_BYTES ((32 + 16) * WSTR * 4)

__device__ float    g_h[2][BATCH][HDIM];   // ping-pong hidden state
__device__ unsigned g_cnt[4];              // barrier arrival counters (reset to 0 each step)
__device__ volatile unsigned g_phase[4];   // barrier phase (toggles; 512 toggles -> back to 0)

__global__ void __launch_bounds__(256, 1) rec_kernel(
    const float* __restrict__ h0,
    const float* __restrict__ Whh,
    float* out)
{
    extern __shared__ float sm[];
    float* Wsm = sm;                 // [32][WSTR]
    float* hsm = sm + 32 * WSTR;     // [16][WSTR]

    const int cta = blockIdx.x;
    const int grp = cta >> 5;        // 0..3 batch group
    const int gc  = cta & 31;        // 0..31 within group
    const int j0  = gc * 32;         // global neuron base for this CTA
    const int b0g = grp * 16;        // global batch base for this group
    const int tid = threadIdx.x;

    // ---- load W_hh rows [j0, j0+32) into SMEM (once) ----
    {
        const float4* W4 = (const float4*)Whh;
        for (int i = tid; i < 32 * 256; i += 256) {
            int r = i >> 8;          // 0..31
            int c = i & 255;         // float4 col
            float4 v = W4[(size_t)(j0 + r) * 256 + c];
            *(float4*)&Wsm[r * WSTR + c * 4] = v;
        }
    }

    // ---- per-thread output mapping: 2 outputs (b0,j) (b0+1,j) ----
    const int w    = tid >> 5, l = tid & 31;
    const int jgrp = w & 3,  bgrp = w >> 2;
    const int jj   = l & 7,  bb   = l >> 3;
    const int jl   = jgrp * 8 + jj;          // 0..31 local neuron
    const int bl   = bgrp * 8 + bb * 2;      // 0..14 (even) local batch
    const int jglob = j0 + jl;
    const int bg0  = b0g + bl;
    const int bg1  = bg0 + 1;

    const float* wp = Wsm + jl * WSTR;
    const float* hpa = hsm + bl * WSTR;
    const float* hpb = hsm + (bl + 1) * WSTR;

    unsigned my_phase = 0;

    for (int t = 0; t < S_LEN; t++) {
        // ---- stage previous hidden state (group's 16 rows) into SMEM ----
        if (t == 0) {
            const float4* H4 = (const float4*)h0;
            for (int i = tid; i < 16 * 256; i += 256) {
                int r = i >> 8, c = i & 255;
                *(float4*)&hsm[r * WSTR + c * 4] = H4[(size_t)(b0g + r) * 256 + c];
            }
        } else {
            const float4* H4 = (const float4*)&g_h[(t - 1) & 1][0][0];
            for (int i = tid; i < 16 * 256; i += 256) {
                int r = i >> 8, c = i & 255;
                float4 v = __ldcv(&H4[(size_t)(b0g + r) * 256 + c]);
                *(float4*)&hsm[r * WSTR + c * 4] = v;
            }
        }
        __syncthreads();

        // ---- dot products: c0 = h[bg0].W[j], c1 = h[bg1].W[j] ----
        float c0 = 0.0f, c1 = 0.0f;
#pragma unroll 4
        for (int k = 0; k < HDIM; k += 4) {
            float4 wv = *(const float4*)(wp + k);
            float4 av = *(const float4*)(hpa + k);
            float4 bv = *(const float4*)(hpb + k);
            c0 = fmaf(wv.x, av.x, c0); c1 = fmaf(wv.x, bv.x, c1);
            c0 = fmaf(wv.y, av.y, c0); c1 = fmaf(wv.y, bv.y, c1);
            c0 = fmaf(wv.z, av.z, c0); c1 = fmaf(wv.z, bv.z, c1);
            c0 = fmaf(wv.w, av.w, c0); c1 = fmaf(wv.w, bv.w, c1);
        }

        // ---- xp (staged in d_out by kernel 1) + relu, write back ----
        int o0 = (bg0 * S_LEN + t) * HDIM + jglob;
        int o1 = (bg1 * S_LEN + t) * HDIM + jglob;
        float x0 = out[o0], x1 = out[o1];
        float h0v = fmaxf(x0 + c0, 0.0f);
        float h1v = fmaxf(x1 + c1, 0.0f);
        out[o0] = h0v;
        out[o1] = h1v;
        g_h[t & 1][bg0][jglob] = h0v;
        g_h[t & 1][bg1][jglob] = h1v;
        if (t == S_LEN - 1) {
            out[OUT_TAIL + bg0 * HDIM + jglob] = h0v;
            out[OUT_TAIL + bg1 * HDIM + jglob] = h1v;
        }

        // ---- group barrier (32 CTAs), sense-reversing ----
        __syncthreads();
        if (tid == 0) {
            __threadfence();  // publish this CTA's stores (post-syncthreads => covers all threads)
            unsigned old = atomicAdd(&g_cnt[grp], 1u);
            if (old == 31u) {
                atomicExch(&g_cnt[grp], 0u);
                __threadfence();
                g_phase[grp] = my_phase ^ 1u;   // release the group
            } else {
                while (g_phase[grp] == my_phase) { __nanosleep(64); }
            }
            __threadfence();  // acquire
        }
        my_phase ^= 1u;
        __syncthreads();
    }
}

// ====================================================================
// Launch
// ====================================================================
extern "C" void kernel_launch(void* const* d_in, const int* in_sizes, int n_in,
                              void* d_out, int out_size)
{
    const float* inputs = (const float*)d_in[0];   // [64,512,1024]
    const float* h0     = (const float*)d_in[1];   // [1,64,1024]
    const float* wih    = (const float*)d_in[2];   // [1024,1024]
    const float* whh    = (const float*)d_in[3];   // [1024,1024]
    const float* bih    = (const float*)d_in[4];   // [1024]
    const float* bhh    = (const float*)d_in[5];   // [1024]
    float* out = (float*)d_out;                    // [64*512*1024 outputs][64*1024 h_last]

    // Kernel 1: xp into outputs region of d_out
    dim3 g1(HDIM / 128, M_TOT / 128);   // (8, 256)
    xproj_kernel<<<g1, 256>>>(inputs, wih, bih, bhh, out);

    // Kernel 2: persistent recurrence (needs >48KB dynamic SMEM)
    cudaFuncSetAttribute(rec_kernel, cudaFuncAttributeMaxDynamicSharedMemorySize,
                         REC_SMEM_BYTES);
    rec_kernel<<<128, 256, REC_SMEM_BYTES>>>(h0, whh, out);
}